// round 7
// baseline (speedup 1.0000x reference)
#include <cuda_runtime.h>

#define NQ 10
#define DEPTH 6
#define NF 1024
#define NC 10

typedef unsigned long long u64;

// ---------- f32x2 packed helpers ----------
__device__ __forceinline__ u64 pk(float x, float y) {
    u64 u; asm("mov.b64 %0,{%1,%2};" : "=l"(u) : "f"(x), "f"(y)); return u;
}
__device__ __forceinline__ u64 dup2(float x) { return pk(x, x); }
__device__ __forceinline__ void unpk(u64 u, float& x, float& y) {
    asm("mov.b64 {%0,%1},%2;" : "=f"(x), "=f"(y) : "l"(u));
}
__device__ __forceinline__ u64 fma2(u64 a, u64 b, u64 c) {
    u64 d; asm("fma.rn.f32x2 %0,%1,%2,%3;" : "=l"(d) : "l"(a), "l"(b), "l"(c)); return d;
}
__device__ __forceinline__ u64 mul2(u64 a, u64 b) {
    u64 d; asm("mul.rn.f32x2 %0,%1,%2;" : "=l"(d) : "l"(a), "l"(b)); return d;
}
__device__ __forceinline__ u64 add2(u64 a, u64 b) {
    u64 d; asm("add.rn.f32x2 %0,%1,%2;" : "=l"(d) : "l"(a), "l"(b)); return d;
}
__device__ __forceinline__ u64 neg2(u64 a) { return a ^ 0x8000000080000000ULL; }
__device__ __forceinline__ u64 rot32(u64 v) { return (v >> 32) | (v << 32); }

#define LOMASK 0x00000000FFFFFFFFULL
#define HIMASK 0xFFFFFFFF00000000ULL
#define FULLM 0xffffffffu

// Amplitude index m (10 bits): bits0-4 = lane, bits5-8 = reg r (0..15), bit9 = u64 half.
// CNOT ring (range R); all category combinations resolved at compile time.
template <int R>
__device__ __forceinline__ void cnot_layer(u64 (&sr)[16], u64 (&si)[16], int lane) {
#pragma unroll
    for (int i = 0; i < NQ; i++) {
        const int c = i;
        const int t = (i + R) % NQ;
        if (c < 5 && t < 5) {
            // lane ctrl / lane target: variable-source shuffle (no selects)
            bool ctrl = (lane >> c) & 1;
            int src = ctrl ? (lane ^ (1 << t)) : lane;
#pragma unroll
            for (int r = 0; r < 16; r++) {
                sr[r] = __shfl_sync(FULLM, sr[r], src);
                si[r] = __shfl_sync(FULLM, si[r], src);
            }
        } else if (c < 5 && t >= 5 && t < 9) {
            // lane ctrl / reg target: predicated u64 swap
            const int tb = 1 << (t - 5);
            bool ctrl = (lane >> c) & 1;
#pragma unroll
            for (int r0 = 0; r0 < 16; r0++)
                if (!(r0 & tb)) {
                    const int r1 = r0 | tb;
                    u64 t0 = sr[r0], t1 = si[r0];
                    sr[r0] = ctrl ? sr[r1] : sr[r0];
                    si[r0] = ctrl ? si[r1] : si[r0];
                    sr[r1] = ctrl ? t0 : sr[r1];
                    si[r1] = ctrl ? t1 : si[r1];
                }
        } else if (c < 5 && t == 9) {
            // lane ctrl / half target: conditional half-swap
            bool ctrl = (lane >> c) & 1;
#pragma unroll
            for (int r = 0; r < 16; r++) {
                u64 rr = rot32(sr[r]), ri = rot32(si[r]);
                sr[r] = ctrl ? rr : sr[r];
                si[r] = ctrl ? ri : si[r];
            }
        } else if (c >= 5 && c < 9 && t < 5) {
            // reg ctrl / lane target
            const int cb = 1 << (c - 5);
#pragma unroll
            for (int r = 0; r < 16; r++)
                if (r & cb) {
                    sr[r] = __shfl_xor_sync(FULLM, sr[r], 1 << t);
                    si[r] = __shfl_xor_sync(FULLM, si[r], 1 << t);
                }
        } else if (c >= 5 && c < 9 && t >= 5 && t < 9) {
            // reg ctrl / reg target: free register rename
            const int cb = 1 << (c - 5), tb = 1 << (t - 5);
#pragma unroll
            for (int r0 = 0; r0 < 16; r0++)
                if ((r0 & cb) && !(r0 & tb)) {
                    const int r1 = r0 | tb;
                    u64 tmp = sr[r0]; sr[r0] = sr[r1]; sr[r1] = tmp;
                    tmp = si[r0]; si[r0] = si[r1]; si[r1] = tmp;
                }
        } else if (c >= 5 && c < 9 && t == 9) {
            // reg ctrl / half target
            const int cb = 1 << (c - 5);
#pragma unroll
            for (int r = 0; r < 16; r++)
                if (r & cb) {
                    sr[r] = rot32(sr[r]);
                    si[r] = rot32(si[r]);
                }
        } else if (c == 9 && t < 5) {
            // half ctrl / lane target: permute only hi halves
#pragma unroll
            for (int r = 0; r < 16; r++) {
                u64 pr_ = __shfl_xor_sync(FULLM, sr[r], 1 << t);
                u64 pi_ = __shfl_xor_sync(FULLM, si[r], 1 << t);
                sr[r] = (sr[r] & LOMASK) | (pr_ & HIMASK);
                si[r] = (si[r] & LOMASK) | (pi_ & HIMASK);
            }
        } else {  // c == 9 && t >= 5 && t < 9: swap hi halves between reg pairs
            const int tb = 1 << (t - 5);
#pragma unroll
            for (int r0 = 0; r0 < 16; r0++)
                if (!(r0 & tb)) {
                    const int r1 = r0 | tb;
                    u64 a = sr[r0], b = sr[r1];
                    sr[r0] = (a & LOMASK) | (b & HIMASK);
                    sr[r1] = (b & LOMASK) | (a & HIMASK);
                    a = si[r0]; b = si[r1];
                    si[r0] = (a & LOMASK) | (b & HIMASK);
                    si[r1] = (b & LOMASK) | (a & HIMASK);
                }
        }
    }
}

// Fully fused: SMEM rot build + per-warp projection + register-resident VQC sim + head.
__global__ __launch_bounds__(256, 2) void fused_kernel(
    const float* __restrict__ x, const float* __restrict__ Wp,
    const float* __restrict__ w, const float* __restrict__ Wout,
    const float* __restrict__ bout, float* __restrict__ out, int B) {
    // SU(2) gate table: srot[g] = (alpha_r, alpha_i, beta_r, beta_i)
    __shared__ float4 srot[DEPTH * NQ];
    const int tid = threadIdx.x;
    if (tid < DEPTH * NQ) {
        float phi = w[tid * 3 + 0], theta = w[tid * 3 + 1], omega = w[tid * 3 + 2];
        float c, s;
        sincosf(0.5f * theta, &s, &c);
        float sp, cp, sm, cm;
        sincosf(-0.5f * (phi + omega), &sp, &cp);  // ep
        sincosf(-0.5f * (phi - omega), &sm, &cm);  // em
        // alpha = ep*c ; beta = -conj(em)*s
        srot[tid] = make_float4(cp * c, sp * c, -cm * s, sm * s);
    }
    __syncthreads();

    const int warp = tid >> 5, lane = tid & 31;
    const int b = blockIdx.x * 8 + warp;
    if (b >= B) return;

    // ---- projection: 10 dots of x[b] with W_proj rows -> tanh -> half-angle trig ----
    float tc[NQ], ts[NQ];
    {
        const float4* xv = (const float4*)(x + (size_t)b * NF);
        float acc[NQ];
#pragma unroll
        for (int q = 0; q < NQ; q++) acc[q] = 0.f;
#pragma unroll
        for (int it = 0; it < 8; it++) {
            float4 xx = xv[it * 32 + lane];
#pragma unroll
            for (int q = 0; q < NQ; q++) {
                float4 ww = __ldg(&((const float4*)(Wp + q * NF))[it * 32 + lane]);
                acc[q] += xx.x * ww.x + xx.y * ww.y + xx.z * ww.z + xx.w * ww.w;
            }
        }
#pragma unroll
        for (int off = 16; off > 0; off >>= 1)
#pragma unroll
            for (int q = 0; q < NQ; q++) acc[q] += __shfl_xor_sync(FULLM, acc[q], off);
        float myc = 0.f, mys = 0.f;
        if (lane < NQ) {
            float v = acc[0];
#pragma unroll
            for (int q = 1; q < NQ; q++)
                if (lane == q) v = acc[q];
            float half = tanhf(v) * 0.78539816339744831f;  // (pi/2)/2
            sincosf(half, &mys, &myc);
        }
#pragma unroll
        for (int q = 0; q < NQ; q++) {
            tc[q] = __shfl_sync(FULLM, myc, q);
            ts[q] = __shfl_sync(FULLM, mys, q);
        }
    }

    // ---- init: RY product state ----
    float pl = 1.f;
#pragma unroll
    for (int q = 0; q < 5; q++) pl *= ((lane >> q) & 1) ? ts[q] : tc[q];
    u64 sr[16], si[16];
#pragma unroll
    for (int r = 0; r < 16; r++) {
        float base = pl;
#pragma unroll
        for (int j = 0; j < 4; j++) base *= ((r >> j) & 1) ? ts[5 + j] : tc[5 + j];
        sr[r] = pk(base * tc[9], base * ts[9]);
        si[r] = 0ULL;
    }

    // ---- layers ----
#pragma unroll 1
    for (int l = 0; l < DEPTH; l++) {
#pragma unroll
        for (int q = 0; q < NQ; q++) {
            float4 G = srot[l * NQ + q];  // (ar, ai, br, bi)
            if (q >= 5 && q < 9) {
                // reg-bit gate, SU(2): n0 = a*x0 + b*x1 ; n1 = -conj(b)*x0 + conj(a)*x1
                u64 Ar = dup2(G.x), Ai = dup2(G.y), Ain = dup2(-G.y);
                u64 Br = dup2(G.z), Brn = dup2(-G.z);
                u64 Bi = dup2(G.w), Bin = dup2(-G.w);
                const int jb = 1 << (q - 5);
#pragma unroll
                for (int r0 = 0; r0 < 16; r0++)
                    if (!(r0 & jb)) {
                        const int r1 = r0 | jb;
                        u64 a0r = sr[r0], a0i = si[r0];
                        u64 a1r = sr[r1], a1i = si[r1];
                        u64 t;
                        t = mul2(Bin, a1i); t = fma2(Br, a1r, t); t = fma2(Ain, a0i, t);
                        sr[r0] = fma2(Ar, a0r, t);
                        t = mul2(Bi, a1r); t = fma2(Br, a1i, t); t = fma2(Ai, a0r, t);
                        si[r0] = fma2(Ar, a0i, t);
                        t = mul2(Bin, a0i); t = fma2(Brn, a0r, t); t = fma2(Ai, a1i, t);
                        sr[r1] = fma2(Ar, a1r, t);
                        t = mul2(Bi, a0r); t = fma2(Brn, a0i, t); t = fma2(Ain, a1r, t);
                        si[r1] = fma2(Ar, a1i, t);
                    }
            } else if (q < 5) {
                // lane-bit gate: mine-coef = (ar, +/-ai), partner-coef = (+/-br, bi)
                bool hi = (lane >> q) & 1;
                float sai = hi ? -G.y : G.y;
                float sbr = hi ? -G.z : G.z;
                u64 Ar = dup2(G.x), Sai = dup2(sai), Sain = dup2(-sai);
                u64 Sbr = dup2(sbr), Bi = dup2(G.w), Bin = dup2(-G.w);
#pragma unroll
                for (int r = 0; r < 16; r++) {
                    u64 pr_ = __shfl_xor_sync(FULLM, sr[r], 1 << q);
                    u64 pi_ = __shfl_xor_sync(FULLM, si[r], 1 << q);
                    u64 mr = sr[r], mi = si[r];
                    u64 t;
                    t = mul2(Bin, pi_); t = fma2(Sbr, pr_, t); t = fma2(Sain, mi, t);
                    sr[r] = fma2(Ar, mr, t);
                    t = mul2(Bi, pr_); t = fma2(Sbr, pi_, t); t = fma2(Sai, mr, t);
                    si[r] = fma2(Ar, mi, t);
                }
            } else {
                // q == 9 (half bit): n = K0 (.) s + K1 (.) rot32(s), complex elementwise
                // K0 = (u00, u11) = (a, conj a); K1 = (u01, u10) = (b, -conj b)
                u64 K0r = dup2(G.x), K0i = pk(G.y, -G.y), K0in = pk(-G.y, G.y);
                u64 K1r = pk(G.z, -G.z), K1i = dup2(G.w), K1in = dup2(-G.w);
#pragma unroll
                for (int r = 0; r < 16; r++) {
                    u64 mr = sr[r], mi = si[r];
                    u64 tr = rot32(mr), ti = rot32(mi);
                    u64 t;
                    t = mul2(K1in, ti); t = fma2(K1r, tr, t); t = fma2(K0in, mi, t);
                    sr[r] = fma2(K0r, mr, t);
                    t = mul2(K1i, tr); t = fma2(K1r, ti, t); t = fma2(K0i, mr, t);
                    si[r] = fma2(K0r, mi, t);
                }
            }
        }
        switch (l) {
            case 0: cnot_layer<1>(sr, si, lane); break;
            case 1: cnot_layer<2>(sr, si, lane); break;
            case 2: cnot_layer<3>(sr, si, lane); break;
            case 3: cnot_layer<4>(sr, si, lane); break;
            case 4: cnot_layer<5>(sr, si, lane); break;
            default: cnot_layer<6>(sr, si, lane); break;
        }
    }

    // ---- Z expvals ----
    u64 S2 = 0ULL, U0 = 0ULL, U1 = 0ULL, U2 = 0ULL, U3 = 0ULL;
#pragma unroll
    for (int r = 0; r < 16; r++) {
        u64 p = fma2(sr[r], sr[r], mul2(si[r], si[r]));
        u64 np = neg2(p);
        S2 = add2(S2, p);
        U0 = add2(U0, (r & 1) ? np : p);
        U1 = add2(U1, (r & 2) ? np : p);
        U2 = add2(U2, (r & 4) ? np : p);
        U3 = add2(U3, (r & 8) ? np : p);
    }
    float slo, shi;
    unpk(S2, slo, shi);
    float Stot = slo + shi;
    float e[NQ];
#pragma unroll
    for (int q = 0; q < 5; q++) e[q] = ((lane >> q) & 1) ? -Stot : Stot;
    {
        float lo, hi;
        unpk(U0, lo, hi); e[5] = lo + hi;
        unpk(U1, lo, hi); e[6] = lo + hi;
        unpk(U2, lo, hi); e[7] = lo + hi;
        unpk(U3, lo, hi); e[8] = lo + hi;
        e[9] = slo - shi;
    }
#pragma unroll
    for (int off = 16; off > 0; off >>= 1)
#pragma unroll
        for (int q = 0; q < NQ; q++) e[q] += __shfl_xor_sync(FULLM, e[q], off);

    // ---- linear head ----
    if (lane < NC) {
        float o = __ldg(&bout[lane]);
#pragma unroll
        for (int q = 0; q < NQ; q++) o += e[q] * __ldg(&Wout[lane * NQ + q]);
        out[(size_t)b * NC + lane] = o;
    }
}

extern "C" void kernel_launch(void* const* d_in, const int* in_sizes, int n_in,
                              void* d_out, int out_size) {
    const float* x = (const float*)d_in[0];        // (B, 1024)
    const float* W_proj = (const float*)d_in[1];   // (10, 1024)
    const float* weights = (const float*)d_in[2];  // (6, 10, 3)
    const float* W_out = (const float*)d_in[3];    // (10, 10)
    const float* b_out = (const float*)d_in[4];    // (10,)
    float* out = (float*)d_out;                    // (B, 10)

    int B = in_sizes[0] / NF;
    int nblk = (B + 7) / 8;

    fused_kernel<<<nblk, 256>>>(x, W_proj, weights, W_out, b_out, out, B);
}

// round 8
// speedup vs baseline: 1.1540x; 1.1540x over previous
#include <cuda_runtime.h>

#define NQ 10
#define DEPTH 6
#define NF 1024
#define NC 10

typedef unsigned long long u64;

// ---------- f32x2 packed helpers ----------
__device__ __forceinline__ u64 pk(float x, float y) {
    u64 u; asm("mov.b64 %0,{%1,%2};" : "=l"(u) : "f"(x), "f"(y)); return u;
}
__device__ __forceinline__ u64 dup2(float x) { return pk(x, x); }
__device__ __forceinline__ void unpk(u64 u, float& x, float& y) {
    asm("mov.b64 {%0,%1},%2;" : "=f"(x), "=f"(y) : "l"(u));
}
__device__ __forceinline__ u64 fma2(u64 a, u64 b, u64 c) {
    u64 d; asm("fma.rn.f32x2 %0,%1,%2,%3;" : "=l"(d) : "l"(a), "l"(b), "l"(c)); return d;
}
__device__ __forceinline__ u64 mul2(u64 a, u64 b) {
    u64 d; asm("mul.rn.f32x2 %0,%1,%2;" : "=l"(d) : "l"(a), "l"(b)); return d;
}
__device__ __forceinline__ u64 add2(u64 a, u64 b) {
    u64 d; asm("add.rn.f32x2 %0,%1,%2;" : "=l"(d) : "l"(a), "l"(b)); return d;
}
__device__ __forceinline__ u64 neg2(u64 a) { return a ^ 0x8000000080000000ULL; }
__device__ __forceinline__ u64 rot32(u64 v) { return (v >> 32) | (v << 32); }

#define LOMASK 0x00000000FFFFFFFFULL
#define HIMASK 0xFFFFFFFF00000000ULL
#define FULLM 0xffffffffu

// lane-parity sign: negate v iff popc(lane & mask) is odd
__device__ __forceinline__ float lsgn(int lane, int mask, float v) {
    return (__popc(lane & mask) & 1) ? -v : v;
}

// Amplitude index m (10 bits): bits0-4 = lane, bits5-8 = reg r (0..15), bit9 = u64 half.
template <int R>
__device__ __forceinline__ void cnot_layer(u64 (&sr)[16], u64 (&si)[16], int lane) {
#pragma unroll
    for (int i = 0; i < NQ; i++) {
        const int c = i;
        const int t = (i + R) % NQ;
        if (c < 5 && t < 5) {
            bool ctrl = (lane >> c) & 1;
            int src = ctrl ? (lane ^ (1 << t)) : lane;
#pragma unroll
            for (int r = 0; r < 16; r++) {
                sr[r] = __shfl_sync(FULLM, sr[r], src);
                si[r] = __shfl_sync(FULLM, si[r], src);
            }
        } else if (c < 5 && t >= 5 && t < 9) {
            const int tb = 1 << (t - 5);
            bool ctrl = (lane >> c) & 1;
#pragma unroll
            for (int r0 = 0; r0 < 16; r0++)
                if (!(r0 & tb)) {
                    const int r1 = r0 | tb;
                    u64 t0 = sr[r0], t1 = si[r0];
                    sr[r0] = ctrl ? sr[r1] : sr[r0];
                    si[r0] = ctrl ? si[r1] : si[r0];
                    sr[r1] = ctrl ? t0 : sr[r1];
                    si[r1] = ctrl ? t1 : si[r1];
                }
        } else if (c < 5 && t == 9) {
            bool ctrl = (lane >> c) & 1;
#pragma unroll
            for (int r = 0; r < 16; r++) {
                u64 rr = rot32(sr[r]), ri = rot32(si[r]);
                sr[r] = ctrl ? rr : sr[r];
                si[r] = ctrl ? ri : si[r];
            }
        } else if (c >= 5 && c < 9 && t < 5) {
            const int cb = 1 << (c - 5);
#pragma unroll
            for (int r = 0; r < 16; r++)
                if (r & cb) {
                    sr[r] = __shfl_xor_sync(FULLM, sr[r], 1 << t);
                    si[r] = __shfl_xor_sync(FULLM, si[r], 1 << t);
                }
        } else if (c >= 5 && c < 9 && t >= 5 && t < 9) {
            const int cb = 1 << (c - 5), tb = 1 << (t - 5);
#pragma unroll
            for (int r0 = 0; r0 < 16; r0++)
                if ((r0 & cb) && !(r0 & tb)) {
                    const int r1 = r0 | tb;
                    u64 tmp = sr[r0]; sr[r0] = sr[r1]; sr[r1] = tmp;
                    tmp = si[r0]; si[r0] = si[r1]; si[r1] = tmp;
                }
        } else if (c >= 5 && c < 9 && t == 9) {
            const int cb = 1 << (c - 5);
#pragma unroll
            for (int r = 0; r < 16; r++)
                if (r & cb) {
                    sr[r] = rot32(sr[r]);
                    si[r] = rot32(si[r]);
                }
        } else if (c == 9 && t < 5) {
#pragma unroll
            for (int r = 0; r < 16; r++) {
                u64 pr_ = __shfl_xor_sync(FULLM, sr[r], 1 << t);
                u64 pi_ = __shfl_xor_sync(FULLM, si[r], 1 << t);
                sr[r] = (sr[r] & LOMASK) | (pr_ & HIMASK);
                si[r] = (si[r] & LOMASK) | (pi_ & HIMASK);
            }
        } else {  // c == 9 && t in [5,9)
            const int tb = 1 << (t - 5);
#pragma unroll
            for (int r0 = 0; r0 < 16; r0++)
                if (!(r0 & tb)) {
                    const int r1 = r0 | tb;
                    u64 a = sr[r0], b = sr[r1];
                    sr[r0] = (a & LOMASK) | (b & HIMASK);
                    sr[r1] = (b & LOMASK) | (a & HIMASK);
                    a = si[r0]; b = si[r1];
                    si[r0] = (a & LOMASK) | (b & HIMASK);
                    si[r1] = (b & LOMASK) | (a & HIMASK);
                }
        }
    }
}

__global__ __launch_bounds__(256, 2) void fused_kernel(
    const float* __restrict__ x, const float* __restrict__ Wp,
    const float* __restrict__ w, const float* __restrict__ Wout,
    const float* __restrict__ bout, float* __restrict__ out, int B) {
    // SU(2) gate table: srot[g] = (alpha_r, alpha_i, beta_r, beta_i)
    __shared__ float4 srot[DEPTH * NQ];
    const int tid = threadIdx.x;
    if (tid < DEPTH * NQ) {
        float phi = w[tid * 3 + 0], theta = w[tid * 3 + 1], omega = w[tid * 3 + 2];
        float c, s;
        sincosf(0.5f * theta, &s, &c);
        float sp, cp, sm, cm;
        sincosf(-0.5f * (phi + omega), &sp, &cp);
        sincosf(-0.5f * (phi - omega), &sm, &cm);
        srot[tid] = make_float4(cp * c, sp * c, -cm * s, sm * s);
    }
    __syncthreads();

    const int warp = tid >> 5, lane = tid & 31;
    const int b = blockIdx.x * 8 + warp;
    if (b >= B) return;

    // ---- projection -> half-angle trig ----
    float tc[NQ], ts[NQ];
    {
        const float4* xv = (const float4*)(x + (size_t)b * NF);
        float acc[NQ];
#pragma unroll
        for (int q = 0; q < NQ; q++) acc[q] = 0.f;
#pragma unroll
        for (int it = 0; it < 8; it++) {
            float4 xx = xv[it * 32 + lane];
#pragma unroll
            for (int q = 0; q < NQ; q++) {
                float4 ww = __ldg(&((const float4*)(Wp + q * NF))[it * 32 + lane]);
                acc[q] += xx.x * ww.x + xx.y * ww.y + xx.z * ww.z + xx.w * ww.w;
            }
        }
#pragma unroll
        for (int off = 16; off > 0; off >>= 1)
#pragma unroll
            for (int q = 0; q < NQ; q++) acc[q] += __shfl_xor_sync(FULLM, acc[q], off);
        float myc = 0.f, mys = 0.f;
        if (lane < NQ) {
            float v = acc[0];
#pragma unroll
            for (int q = 1; q < NQ; q++)
                if (lane == q) v = acc[q];
            float half = tanhf(v) * 0.78539816339744831f;
            sincosf(half, &mys, &myc);
        }
#pragma unroll
        for (int q = 0; q < NQ; q++) {
            tc[q] = __shfl_sync(FULLM, myc, q);
            ts[q] = __shfl_sync(FULLM, mys, q);
        }
    }

    // ---- init: RY product state with layer-0 Rot folded in ----
    // per-qubit complex 2-vector: v0 = alpha*c + beta*s ; v1 = -conj(beta)*c + conj(alpha)*s
    float v0r[NQ], v0i[NQ], v1r[NQ], v1i[NQ];
#pragma unroll
    for (int q = 0; q < NQ; q++) {
        float4 G = srot[q];  // layer 0 gate for qubit q
        v0r[q] = G.x * tc[q] + G.z * ts[q];
        v0i[q] = G.y * tc[q] + G.w * ts[q];
        v1r[q] = -G.z * tc[q] + G.x * ts[q];
        v1i[q] = G.w * tc[q] - G.y * ts[q];
    }
    // lane product over qubits 0..4 (complex)
    float plr, pli;
    {
        bool b0 = lane & 1;
        plr = b0 ? v1r[0] : v0r[0];
        pli = b0 ? v1i[0] : v0i[0];
#pragma unroll
        for (int q = 1; q < 5; q++) {
            bool bq = (lane >> q) & 1;
            float wr = bq ? v1r[q] : v0r[q];
            float wi = bq ? v1i[q] : v0i[q];
            float nr = plr * wr - pli * wi;
            float ni = plr * wi + pli * wr;
            plr = nr; pli = ni;
        }
    }
    // reg products over qubits 5..8
    float rpr[16], rpi[16];
    {
        float ar2[4], ai2[4], br2[4], bi2[4];
#pragma unroll
        for (int k = 0; k < 4; k++) {
            float x5r = (k & 1) ? v1r[5] : v0r[5], x5i = (k & 1) ? v1i[5] : v0i[5];
            float x6r = (k & 2) ? v1r[6] : v0r[6], x6i = (k & 2) ? v1i[6] : v0i[6];
            ar2[k] = x5r * x6r - x5i * x6i;
            ai2[k] = x5r * x6i + x5i * x6r;
            float x7r = (k & 1) ? v1r[7] : v0r[7], x7i = (k & 1) ? v1i[7] : v0i[7];
            float x8r = (k & 2) ? v1r[8] : v0r[8], x8i = (k & 2) ? v1i[8] : v0i[8];
            br2[k] = x7r * x8r - x7i * x8i;
            bi2[k] = x7r * x8i + x7i * x8r;
        }
#pragma unroll
        for (int r = 0; r < 16; r++) {
            float lr = ar2[r & 3], li = ai2[r & 3];
            float hr = br2[r >> 2], hi = bi2[r >> 2];
            rpr[r] = lr * hr - li * hi;
            rpi[r] = lr * hi + li * hr;
        }
    }
    u64 sr[16], si[16];
    {
        u64 V9r = pk(v0r[9], v1r[9]);
        u64 V9i = pk(v0i[9], v1i[9]);
#pragma unroll
        for (int r = 0; r < 16; r++) {
            float baser = plr * rpr[r] - pli * rpi[r];
            float basei = plr * rpi[r] + pli * rpr[r];
            u64 br_ = dup2(baser), bi_ = dup2(basei);
            sr[r] = fma2(br_, V9r, neg2(mul2(bi_, V9i)));
            si[r] = fma2(br_, V9i, mul2(bi_, V9r));
        }
    }

    // ---- layer 0 entangler, then layers 1..5 (last CNOT ring folded into expvals) ----
    cnot_layer<1>(sr, si, lane);
#pragma unroll 1
    for (int l = 1; l < DEPTH; l++) {
#pragma unroll
        for (int q = 0; q < NQ; q++) {
            float4 G = srot[l * NQ + q];
            if (q >= 5 && q < 9) {
                u64 Ar = dup2(G.x), Ai = dup2(G.y), Ain = dup2(-G.y);
                u64 Br = dup2(G.z), Brn = dup2(-G.z);
                u64 Bi = dup2(G.w), Bin = dup2(-G.w);
                const int jb = 1 << (q - 5);
#pragma unroll
                for (int r0 = 0; r0 < 16; r0++)
                    if (!(r0 & jb)) {
                        const int r1 = r0 | jb;
                        u64 a0r = sr[r0], a0i = si[r0];
                        u64 a1r = sr[r1], a1i = si[r1];
                        u64 t;
                        t = mul2(Bin, a1i); t = fma2(Br, a1r, t); t = fma2(Ain, a0i, t);
                        sr[r0] = fma2(Ar, a0r, t);
                        t = mul2(Bi, a1r); t = fma2(Br, a1i, t); t = fma2(Ai, a0r, t);
                        si[r0] = fma2(Ar, a0i, t);
                        t = mul2(Bin, a0i); t = fma2(Brn, a0r, t); t = fma2(Ai, a1i, t);
                        sr[r1] = fma2(Ar, a1r, t);
                        t = mul2(Bi, a0r); t = fma2(Brn, a0i, t); t = fma2(Ain, a1r, t);
                        si[r1] = fma2(Ar, a1i, t);
                    }
            } else if (q < 5) {
                bool hi = (lane >> q) & 1;
                float sai = hi ? -G.y : G.y;
                float sbr = hi ? -G.z : G.z;
                u64 Ar = dup2(G.x), Sai = dup2(sai), Sain = dup2(-sai);
                u64 Sbr = dup2(sbr), Bi = dup2(G.w), Bin = dup2(-G.w);
#pragma unroll
                for (int r = 0; r < 16; r++) {
                    u64 pr_ = __shfl_xor_sync(FULLM, sr[r], 1 << q);
                    u64 pi_ = __shfl_xor_sync(FULLM, si[r], 1 << q);
                    u64 mr = sr[r], mi = si[r];
                    u64 t;
                    t = mul2(Bin, pi_); t = fma2(Sbr, pr_, t); t = fma2(Sain, mi, t);
                    sr[r] = fma2(Ar, mr, t);
                    t = mul2(Bi, pr_); t = fma2(Sbr, pi_, t); t = fma2(Sai, mr, t);
                    si[r] = fma2(Ar, mi, t);
                }
            } else {  // q == 9
                u64 K0r = dup2(G.x), K0i = pk(G.y, -G.y), K0in = pk(-G.y, G.y);
                u64 K1r = pk(G.z, -G.z), K1i = dup2(G.w), K1in = dup2(-G.w);
#pragma unroll
                for (int r = 0; r < 16; r++) {
                    u64 mr = sr[r], mi = si[r];
                    u64 tr = rot32(mr), ti = rot32(mi);
                    u64 t;
                    t = mul2(K1in, ti); t = fma2(K1r, tr, t); t = fma2(K0in, mi, t);
                    sr[r] = fma2(K0r, mr, t);
                    t = mul2(K1i, tr); t = fma2(K1r, ti, t); t = fma2(K0i, mr, t);
                    si[r] = fma2(K0r, mi, t);
                }
            }
        }
        // entangler for layers 1..4; layer 5's R=6 ring is folded into the expvals below
        switch (l) {
            case 1: cnot_layer<2>(sr, si, lane); break;
            case 2: cnot_layer<3>(sr, si, lane); break;
            case 3: cnot_layer<4>(sr, si, lane); break;
            case 4: cnot_layer<5>(sr, si, lane); break;
            default: break;
        }
    }

    // ---- Z expvals with R=6 CNOT ring folded in as GF(2) parity masks ----
    // masks (qubit-bit sets): m0={0,4} m1={1,5} m2={0,2,6} m3={1,3,7} m4={2,4,8}
    //                         m5={3,5,9} m6={0,6} m7={1,7} m8={2,8} m9={3,9}
    u64 A0 = 0ULL, A1 = 0ULL, A2 = 0ULL, A4 = 0ULL, A8 = 0ULL;
#pragma unroll
    for (int r = 0; r < 16; r++) {
        u64 p = fma2(sr[r], sr[r], mul2(si[r], si[r]));
        u64 np = neg2(p);
        A0 = add2(A0, p);
        A1 = add2(A1, (r & 1) ? np : p);
        A2 = add2(A2, (r & 2) ? np : p);
        A4 = add2(A4, (r & 4) ? np : p);
        A8 = add2(A8, (r & 8) ? np : p);
    }
    float e[NQ];
    {
        float lo, hi;
        unpk(A0, lo, hi);
        e[0] = lsgn(lane, 0x11, lo + hi);   // {0,4}
        e[9] = lsgn(lane, 0x08, lo - hi);   // {3} + half
        unpk(A1, lo, hi);
        e[1] = lsgn(lane, 0x02, lo + hi);   // {1} + reg5
        e[5] = lsgn(lane, 0x08, lo - hi);   // {3} + reg5 + half
        unpk(A2, lo, hi);
        e[2] = lsgn(lane, 0x05, lo + hi);   // {0,2} + reg6
        e[6] = lsgn(lane, 0x01, lo + hi);   // {0} + reg6
        unpk(A4, lo, hi);
        e[3] = lsgn(lane, 0x0A, lo + hi);   // {1,3} + reg7
        e[7] = lsgn(lane, 0x02, lo + hi);   // {1} + reg7
        unpk(A8, lo, hi);
        e[4] = lsgn(lane, 0x14, lo + hi);   // {2,4} + reg8
        e[8] = lsgn(lane, 0x04, lo + hi);   // {2} + reg8
    }
#pragma unroll
    for (int off = 16; off > 0; off >>= 1)
#pragma unroll
        for (int q = 0; q < NQ; q++) e[q] += __shfl_xor_sync(FULLM, e[q], off);

    // ---- linear head ----
    if (lane < NC) {
        float o = __ldg(&bout[lane]);
#pragma unroll
        for (int q = 0; q < NQ; q++) o += e[q] * __ldg(&Wout[lane * NQ + q]);
        out[(size_t)b * NC + lane] = o;
    }
}

extern "C" void kernel_launch(void* const* d_in, const int* in_sizes, int n_in,
                              void* d_out, int out_size) {
    const float* x = (const float*)d_in[0];
    const float* W_proj = (const float*)d_in[1];
    const float* weights = (const float*)d_in[2];
    const float* W_out = (const float*)d_in[3];
    const float* b_out = (const float*)d_in[4];
    float* out = (float*)d_out;

    int B = in_sizes[0] / NF;
    int nblk = (B + 7) / 8;

    fused_kernel<<<nblk, 256>>>(x, W_proj, weights, W_out, b_out, out, B);
}